// round 7
// baseline (speedup 1.0000x reference)
#include <cuda_runtime.h>

#define BB 64
#define CC 512
#define HH 28
#define WW 28
#define HWSZ (HH*WW)
#define HID 32
#define NPLANE (BB*CC)
#define NLAYERS 4
#define QPP 196            // float4 quads per plane
#define PPB 8              // planes per block (1 warp each)
#define NUP (NPLANE/PPB)   // 4096 producer blocks
#define BPB 64             // producer blocks per batch (512/PPB)

// Scratch (static device memory -- allocation-free)
__device__ float g_buf[(size_t)NPLANE * HWSZ];   // ping-pong x buffer (~103MB)
__device__ float g_seq[NPLANE];                  // pooled means [B,C]
__device__ float g_H[2][NPLANE];                 // LSTM hidden (double-buffered)
__device__ float g_C[2][NPLANE];                 // LSTM cell   (double-buffered)
__device__ float g_GI[2][BB * 3 * CC];           // input-path gates
__device__ float g_GH2[2][3 * CC];               // 2nd-cell hidden gates (row 0)
__device__ int   g_cnt[4][BB * 32];              // per-(kernel,batch) arrival counters

__device__ __forceinline__ float sigmf(float x) { return 1.0f / (1.0f + __expf(-x)); }
__device__ __forceinline__ float tanhfast(float x) {
    float e = __expf(2.0f * x);
    return __fdividef(e - 1.0f, e + 1.0f);
}

// ---------------- cell body: one block (256 thr) handles batch b ----------------
// Waits until all BPB producer blocks of batch b have arrived (counter), then
// computes both bottleneck GEMVs + gate update; block for b==0 also computes the
// second cell's hidden path (ht[0] -> g_GH2[ws]).
__device__ void cell_body(int b, int ws, int zeroState, int slot,
        const float* __restrict__ w_ih_l1, const float* __restrict__ b_ih_l1,
        const float* __restrict__ w_ih_l2, const float* __restrict__ b_ih_l2,
        const float* __restrict__ w_hh_l1, const float* __restrict__ b_hh_l1,
        const float* __restrict__ w_hh_l2, const float* __restrict__ b_hh_l2) {
    __shared__ __align__(16) float sin0[CC], sin1[CC];
    __shared__ float hi[HID], hh[HID];
    int tid = threadIdx.x, lane = tid & 31, w = tid >> 5;   // 8 warps
    int rs = 1 - ws;

    // preload ht (previous kernel's data) or zeros
    if (tid < 128) {
        float4 hv = zeroState ? make_float4(0.f, 0.f, 0.f, 0.f)
                              : ((const float4*)(g_H[rs] + b * CC))[tid];
        ((float4*)sin1)[tid] = hv;
    }
    // spin until this batch's producers are done
    if (tid == 0) {
        int* cnt = &g_cnt[slot][b * 32];
        while (atomicAdd(cnt, 0) < BPB) __nanosleep(64);
        atomicExch(cnt, 0);          // reset for next graph replay
        __threadfence();
    }
    __syncthreads();
    // seq written by producers in THIS kernel -> read via L2
    if (tid < 128) ((float4*)sin0)[tid] = __ldcg(((const float4*)(g_seq + b * CC)) + tid);
    __syncthreads();

    // Phase 1: 64 dots of length 512 (2 paths x 32 hidden), 8 warps x 8 rounds.
    #pragma unroll
    for (int t = 0; t < 8; t++) {
        int d = t * 8 + w;
        int path = d >> 5, k = d & 31;
        const float4* wr4 = (const float4*)((path ? w_hh_l1 : w_ih_l1) + k * CC);
        const float4* in4 = (const float4*)(path ? sin1 : sin0);
        float s = 0.f;
        #pragma unroll
        for (int j = lane; j < 128; j += 32) {
            float4 wv = wr4[j], iv = in4[j];
            s += iv.x * wv.x + iv.y * wv.y + iv.z * wv.z + iv.w * wv.w;
        }
        #pragma unroll
        for (int o = 16; o; o >>= 1) s += __shfl_down_sync(0xffffffffu, s, o);
        if (lane == 0) {
            float v = fmaxf(s + (path ? b_hh_l1 : b_ih_l1)[k], 0.f);
            if (path) hh[k] = v; else hi[k] = v;
        }
    }
    __syncthreads();

    // Phase 2: two channels per thread (c = tid, tid+256).
    #pragma unroll
    for (int half = 0; half < 2; half++) {
        int c = tid + half * 256;
        float gi[3], gh[3];
        #pragma unroll
        for (int g = 0; g < 3; g++) { gi[g] = b_ih_l2[g * CC + c]; gh[g] = b_hh_l2[g * CC + c]; }
        #pragma unroll
        for (int g = 0; g < 3; g++) {
            const float4* wi4 = (const float4*)&w_ih_l2[(g * CC + c) * HID];
            const float4* wh4 = (const float4*)&w_hh_l2[(g * CC + c) * HID];
            #pragma unroll
            for (int q = 0; q < 8; q++) {
                float4 wi = wi4[q], wh = wh4[q];
                int k = q * 4;
                gi[g] += hi[k] * wi.x + hi[k+1] * wi.y + hi[k+2] * wi.z + hi[k+3] * wi.w;
                gh[g] += hh[k] * wh.x + hh[k+1] * wh.y + hh[k+2] * wh.z + hh[k+3] * wh.w;
            }
        }
        #pragma unroll
        for (int g = 0; g < 3; g++) g_GI[ws][(b * 3 + g) * CC + c] = gi[g];
        float ig = sigmf(gi[0] + gh[0]);
        float fg = sigmf(gi[1] + gh[1]);
        float cg = tanhfast(gi[2] + gh[2]);
        float cx = zeroState ? 0.f : g_C[rs][b * CC + c];
        float nc = fg * cx + ig * cg;
        float nh = sigmf(nc);
        g_C[ws][b * CC + c] = nc;
        g_H[ws][b * CC + c] = nh;
        if (b == 0) sin0[c] = nh;
    }

    // Tail (batch 0 only): hid2 = relu(W1h ht[0] + b1h); g_GH2 = W2h hid2 + b2h.
    if (b == 0) {
        __syncthreads();
        #pragma unroll
        for (int t = 0; t < 4; t++) {
            int k = t * 8 + w;
            const float4* wr4 = (const float4*)(w_hh_l1 + k * CC);
            const float4* in4 = (const float4*)sin0;
            float s = 0.f;
            #pragma unroll
            for (int j = lane; j < 128; j += 32) {
                float4 wv = wr4[j], iv = in4[j];
                s += iv.x * wv.x + iv.y * wv.y + iv.z * wv.z + iv.w * wv.w;
            }
            #pragma unroll
            for (int o = 16; o; o >>= 1) s += __shfl_down_sync(0xffffffffu, s, o);
            if (lane == 0) hi[k] = fmaxf(s + b_hh_l1[k], 0.f);
        }
        __syncthreads();
        #pragma unroll
        for (int j = tid; j < 3 * CC; j += 256) {
            float acc = b_hh_l2[j];
            const float4* wh4 = (const float4*)&w_hh_l2[j * HID];
            #pragma unroll
            for (int q = 0; q < 8; q++) {
                float4 wh = wh4[q];
                int k = q * 4;
                acc += hi[k] * wh.x + hi[k+1] * wh.y + hi[k+2] * wh.z + hi[k+3] * wh.w;
            }
            g_GH2[ws][j] = acc;
        }
    }
}

// ---------------- pool + cell0 ----------------
__global__ void __launch_bounds__(256) k_pool_cell(const float* __restrict__ x,
        const float* __restrict__ w_ih_l1, const float* __restrict__ b_ih_l1,
        const float* __restrict__ w_ih_l2, const float* __restrict__ b_ih_l2,
        const float* __restrict__ w_hh_l1, const float* __restrict__ b_hh_l1,
        const float* __restrict__ w_hh_l2, const float* __restrict__ b_hh_l2) {
    if (blockIdx.x < NUP) {
        int lane = threadIdx.x & 31, w = threadIdx.x >> 5;
        int plane = blockIdx.x * PPB + w;
        const float4* in4 = (const float4*)(x + (size_t)plane * HWSZ);
        float s = 0.f;
        #pragma unroll
        for (int q = lane; q < QPP; q += 32) {
            float4 v = in4[q];
            s += v.x + v.y + v.z + v.w;
        }
        #pragma unroll
        for (int o = 16; o; o >>= 1) s += __shfl_down_sync(0xffffffffu, s, o);
        if (lane == 0) g_seq[plane] = s * (1.0f / HWSZ);
        __syncthreads();
        if (threadIdx.x == 0) {
            __threadfence();
            atomicAdd(&g_cnt[0][(blockIdx.x / BPB) * 32], 1);
        }
    } else {
        cell_body(blockIdx.x - NUP, /*ws=*/0, /*zeroState=*/1, /*slot=*/0,
                  w_ih_l1, b_ih_l1, w_ih_l2, b_ih_l2,
                  w_hh_l1, b_hh_l1, w_hh_l2, b_hh_l2);
    }
}

// ---------------- update_l (+ cell_{l+1}) ----------------
// Producer blocks: warp-per-plane rolling stencil, then arrive on counter.
// Trailing 64 blocks (when doCell): cell for the next layer.
__global__ void __launch_bounds__(256) k_update_cell(
        const float* __restrict__ xin, float* __restrict__ xout,
        const float* __restrict__ dw, int rs, int slot, int doCell,
        const float* __restrict__ w_ih_l1, const float* __restrict__ b_ih_l1,
        const float* __restrict__ w_ih_l2, const float* __restrict__ b_ih_l2,
        const float* __restrict__ w_hh_l1, const float* __restrict__ b_hh_l1,
        const float* __restrict__ w_hh_l2, const float* __restrict__ b_hh_l2) {
    if (blockIdx.x >= NUP) {
        cell_body(blockIdx.x - NUP, /*ws=*/1 - rs, /*zeroState=*/0, slot,
                  w_ih_l1, b_ih_l1, w_ih_l2, b_ih_l2,
                  w_hh_l1, b_hh_l1, w_hh_l2, b_hh_l2);
        return;
    }
    __shared__ __align__(16) float s[PPB * HWSZ + 4];
    int lane = threadIdx.x & 31, w = threadIdx.x >> 5;
    int plane = blockIdx.x * PPB + w;
    int b = plane >> 9, c = plane & 511;
    float* sp = s + w * HWSZ;

    const float4* in4 = (const float4*)(xin + (size_t)plane * HWSZ);
    float4* sp4 = (float4*)sp;
    #pragma unroll
    for (int q = lane; q < QPP; q += 32) sp4[q] = in4[q];

    // second-cell scale, lane-parallel gate loads
    float tg = 0.f;
    if (lane < 3) tg = g_GI[rs][(b * 3 + lane) * CC + c] + g_GH2[rs][lane * CC + c];
    else if (lane == 3) tg = g_C[rs][c];
    float i2  = __shfl_sync(0xffffffffu, tg, 0);
    float f2  = __shfl_sync(0xffffffffu, tg, 1);
    float c2  = __shfl_sync(0xffffffffu, tg, 2);
    float ct0 = __shfl_sync(0xffffffffu, tg, 3);
    float scale = 1.0f + sigmf(sigmf(f2) * ct0 + sigmf(i2) * tanhfast(c2));

    float wq[9];
    const float* wp = dw + c * 9;
    #pragma unroll
    for (int q = 0; q < 9; q++) wq[q] = wp[q];

    __syncwarp();

    int x = lane;
    bool active = x < WW;
    int xi = active ? x : 0;
    bool notL = (x > 0), notR = (x < WW - 1);

    float aL = 0, aC = 0, aR = 0, bL, bC, bR, cL, cC, cR;
    bC = sp[xi];
    bL = __shfl_up_sync(0xffffffffu, bC, 1);   if (!notL) bL = 0;
    bR = __shfl_down_sync(0xffffffffu, bC, 1); if (!notR) bR = 0;
    cC = sp[WW + xi];
    cL = __shfl_up_sync(0xffffffffu, cC, 1);   if (!notL) cL = 0;
    cR = __shfl_down_sync(0xffffffffu, cC, 1); if (!notR) cR = 0;

    float* outp = xout + (size_t)plane * HWSZ;
    float sum = 0.f;
    #pragma unroll
    for (int y = 0; y < HH; y++) {
        float conv = wq[0] * aL + wq[1] * aC + wq[2] * aR
                   + wq[3] * bL + wq[4] * bC + wq[5] * bR
                   + wq[6] * cL + wq[7] * cC + wq[8] * cR;
        float o = fmaf(bC, scale, conv);
        if (active) { outp[y * WW + x] = o; sum += o; }
        aL = bL; aC = bC; aR = bR;
        bL = cL; bC = cC; bR = cR;
        if (y + 2 < HH) {
            cC = sp[(y + 2) * WW + xi];
            cL = __shfl_up_sync(0xffffffffu, cC, 1);   if (!notL) cL = 0;
            cR = __shfl_down_sync(0xffffffffu, cC, 1); if (!notR) cR = 0;
        } else { cC = cL = cR = 0.f; }
    }
    if (doCell) {
        #pragma unroll
        for (int o2 = 16; o2; o2 >>= 1) sum += __shfl_down_sync(0xffffffffu, sum, o2);
        if (lane == 0) g_seq[plane] = sum * (1.0f / HWSZ);
        __syncthreads();
        if (threadIdx.x == 0) {
            __threadfence();
            atomicAdd(&g_cnt[slot][(blockIdx.x / BPB) * 32], 1);
        }
    }
}

extern "C" void kernel_launch(void* const* d_in, const int* in_sizes, int n_in,
                              void* d_out, int out_size) {
    const float* x        = (const float*)d_in[0];
    const float* w_ih_l1  = (const float*)d_in[1];
    const float* b_ih_l1  = (const float*)d_in[2];
    const float* w_ih_l2  = (const float*)d_in[3];
    const float* b_ih_l2  = (const float*)d_in[4];
    const float* w_hh_l1  = (const float*)d_in[5];
    const float* b_hh_l1  = (const float*)d_in[6];
    const float* w_hh_l2  = (const float*)d_in[7];
    const float* b_hh_l2  = (const float*)d_in[8];
    const float* dw       = (const float*)d_in[9];
    float* out = (float*)d_out;

    float* buf = nullptr;
    cudaGetSymbolAddress((void**)&buf, g_buf);

    // pool + cell0 (cell writes slot ws=0)
    k_pool_cell<<<NUP + BB, 256>>>(x, w_ih_l1, b_ih_l1, w_ih_l2, b_ih_l2,
                                   w_hh_l1, b_hh_l1, w_hh_l2, b_hh_l2);

    const float* cur = x;
    for (int l = 0; l < NLAYERS; l++) {
        int doCell = (l < NLAYERS - 1) ? 1 : 0;
        int rs = l & 1;                 // cell_l wrote slot l%2
        float* nxt = ((l & 1) == 0) ? buf : out;   // l0->buf, l1->out, l2->buf, l3->out
        int grid = NUP + (doCell ? BB : 0);
        k_update_cell<<<grid, 256>>>(cur, nxt, dw, rs, l + 1, doCell,
                                     w_ih_l1, b_ih_l1, w_ih_l2, b_ih_l2,
                                     w_hh_l1, b_hh_l1, w_hh_l2, b_hh_l2);
        cur = nxt;
    }
}

// round 9
// speedup vs baseline: 1.6202x; 1.6202x over previous
#include <cuda_runtime.h>

#define BB 64
#define CC 512
#define HH 28
#define WW 28
#define HWSZ (HH*WW)
#define HID 32
#define NPLANE (BB*CC)
#define NLAYERS 4
#define QPP 196            // float4 quads per plane
#define PPB 8              // planes per block (1 warp each)
#define NUP (NPLANE/PPB)   // 4096 update blocks

// Scratch (static device memory -- allocation-free)
__device__ float g_buf[(size_t)NPLANE * HWSZ];   // ping-pong x buffer (~103MB)
__device__ float g_seq[NPLANE];                  // pooled means [B,C]
__device__ float g_H[2][NPLANE];                 // LSTM hidden (double-buffered)
__device__ float g_C[2][NPLANE];                 // LSTM cell
__device__ float g_GI[2][BB * 3 * CC];           // input-path gates
__device__ float g_GH2[2][3 * CC];               // 2nd-cell hidden gates (row 0)

__device__ __forceinline__ float sigmf(float x) { return 1.0f / (1.0f + __expf(-x)); }
__device__ __forceinline__ float tanhfast(float x) {
    float e = __expf(2.0f * x);
    return __fdividef(e - 1.0f, e + 1.0f);
}

// ---------------- pool: warp-per-plane mean of x ----------------
__global__ void __launch_bounds__(256) k_pool(const float* __restrict__ x) {
    int lane = threadIdx.x & 31, w = threadIdx.x >> 5;
    int plane = blockIdx.x * PPB + w;
    const float4* in4 = (const float4*)(x + (size_t)plane * HWSZ);
    float s = 0.f;
    #pragma unroll
    for (int q = lane; q < QPP; q += 32) {
        float4 v = in4[q];
        s += v.x + v.y + v.z + v.w;
    }
    #pragma unroll
    for (int o = 16; o; o >>= 1) s += __shfl_down_sync(0xffffffffu, s, o);
    if (lane == 0) g_seq[plane] = s * (1.0f / HWSZ);
    cudaTriggerProgrammaticLaunchCompletion();
}

// ---------------- cell: one block per batch, 512 threads ----------------
// Pre-sync: everything that depends only on the PREVIOUS cell (ht/ct) --
// hidden-path GEMV + phase-2 gh dots. Post-sync: seq-dependent input path,
// gates, state update; block 0 also the second cell's hidden path.
__global__ void __launch_bounds__(512) k_cell(int ws, int zeroState,
        const float* __restrict__ w_ih_l1, const float* __restrict__ b_ih_l1,
        const float* __restrict__ w_ih_l2, const float* __restrict__ b_ih_l2,
        const float* __restrict__ w_hh_l1, const float* __restrict__ b_hh_l1,
        const float* __restrict__ w_hh_l2, const float* __restrict__ b_hh_l2) {
    __shared__ __align__(16) float sin0[CC], sin1[CC];
    __shared__ float hh[HID], hi[HID];
    int b = blockIdx.x, tid = threadIdx.x, lane = tid & 31, w = tid >> 5;  // 16 warps
    int rs = 1 - ws;

    // ---- pre-sync phase (independent of preceding update kernel) ----
    if (tid < 128) {
        float4 hv = zeroState ? make_float4(0.f, 0.f, 0.f, 0.f)
                              : ((const float4*)(g_H[rs] + b * CC))[tid];
        ((float4*)sin1)[tid] = hv;
    }
    __syncthreads();

    // hidden-path GEMV: 32 dots of length 512
    #pragma unroll
    for (int t = 0; t < 2; t++) {
        int k = t * 16 + w;
        const float4* wr4 = (const float4*)(w_hh_l1 + k * CC);
        const float4* in4 = (const float4*)sin1;
        float s = 0.f;
        #pragma unroll
        for (int j = lane; j < 128; j += 32) {
            float4 wv = wr4[j], iv = in4[j];
            s += iv.x * wv.x + iv.y * wv.y + iv.z * wv.z + iv.w * wv.w;
        }
        #pragma unroll
        for (int o = 16; o; o >>= 1) s += __shfl_down_sync(0xffffffffu, s, o);
        if (lane == 0) hh[k] = fmaxf(s + b_hh_l1[k], 0.f);
    }
    __syncthreads();

    // phase-2 hidden dots per channel (c = tid)
    int c = tid;
    float gh[3], gi[3];
    #pragma unroll
    for (int g = 0; g < 3; g++) { gh[g] = b_hh_l2[g * CC + c]; gi[g] = b_ih_l2[g * CC + c]; }
    #pragma unroll
    for (int g = 0; g < 3; g++) {
        const float4* wh4 = (const float4*)&w_hh_l2[(g * CC + c) * HID];
        #pragma unroll
        for (int q = 0; q < 8; q++) {
            float4 wh = wh4[q];
            int k = q * 4;
            gh[g] += hh[k] * wh.x + hh[k+1] * wh.y + hh[k+2] * wh.z + hh[k+3] * wh.w;
        }
    }
    float cx = zeroState ? 0.f : g_C[rs][b * CC + c];

    // ---- wait for preceding update kernel (seq ready), then let successor start ----
    cudaGridDependencySynchronize();
    cudaTriggerProgrammaticLaunchCompletion();

    if (tid < 128) ((float4*)sin0)[tid] = ((const float4*)(g_seq + b * CC))[tid];
    __syncthreads();

    // input-path GEMV
    #pragma unroll
    for (int t = 0; t < 2; t++) {
        int k = t * 16 + w;
        const float4* wr4 = (const float4*)(w_ih_l1 + k * CC);
        const float4* in4 = (const float4*)sin0;
        float s = 0.f;
        #pragma unroll
        for (int j = lane; j < 128; j += 32) {
            float4 wv = wr4[j], iv = in4[j];
            s += iv.x * wv.x + iv.y * wv.y + iv.z * wv.z + iv.w * wv.w;
        }
        #pragma unroll
        for (int o = 16; o; o >>= 1) s += __shfl_down_sync(0xffffffffu, s, o);
        if (lane == 0) hi[k] = fmaxf(s + b_ih_l1[k], 0.f);
    }
    __syncthreads();

    #pragma unroll
    for (int g = 0; g < 3; g++) {
        const float4* wi4 = (const float4*)&w_ih_l2[(g * CC + c) * HID];
        #pragma unroll
        for (int q = 0; q < 8; q++) {
            float4 wi = wi4[q];
            int k = q * 4;
            gi[g] += hi[k] * wi.x + hi[k+1] * wi.y + hi[k+2] * wi.z + hi[k+3] * wi.w;
        }
        g_GI[ws][(b * 3 + g) * CC + c] = gi[g];
    }
    float ig = sigmf(gi[0] + gh[0]);
    float fg = sigmf(gi[1] + gh[1]);
    float cg = tanhfast(gi[2] + gh[2]);
    float nc = fg * cx + ig * cg;
    float nh = sigmf(nc);
    g_C[ws][b * CC + c] = nc;
    g_H[ws][b * CC + c] = nh;

    // block-0 tail: second cell's hidden path with hx = ht[0]
    if (b == 0) {
        sin1[c] = nh;
        __syncthreads();
        #pragma unroll
        for (int t = 0; t < 2; t++) {
            int k = t * 16 + w;
            const float4* wr4 = (const float4*)(w_hh_l1 + k * CC);
            const float4* in4 = (const float4*)sin1;
            float s = 0.f;
            #pragma unroll
            for (int j = lane; j < 128; j += 32) {
                float4 wv = wr4[j], iv = in4[j];
                s += iv.x * wv.x + iv.y * wv.y + iv.z * wv.z + iv.w * wv.w;
            }
            #pragma unroll
            for (int o = 16; o; o >>= 1) s += __shfl_down_sync(0xffffffffu, s, o);
            if (lane == 0) hh[k] = fmaxf(s + b_hh_l1[k], 0.f);
        }
        __syncthreads();
        #pragma unroll
        for (int j = tid; j < 3 * CC; j += 512) {
            float acc = b_hh_l2[j];
            const float4* wh4 = (const float4*)&w_hh_l2[j * HID];
            #pragma unroll
            for (int q = 0; q < 8; q++) {
                float4 wh = wh4[q];
                int k = q * 4;
                acc += hh[k] * wh.x + hh[k+1] * wh.y + hh[k+2] * wh.z + hh[k+3] * wh.w;
            }
            g_GH2[ws][j] = acc;
        }
    }
}

// ---------------- update: warp-per-plane rolling stencil ----------------
// Pre-sync: stage planes (xin written two kernels back) + conv weights.
// Post-sync: gates (fresh from cell), stencil, write, plane mean.
__global__ void __launch_bounds__(256) k_update(
        const float* __restrict__ xin, float* __restrict__ xout,
        const float* __restrict__ dw, int rs, int writeSeq) {
    __shared__ __align__(16) float s[PPB * HWSZ + 4];
    int lane = threadIdx.x & 31, w = threadIdx.x >> 5;
    int plane = blockIdx.x * PPB + w;
    int b = plane >> 9, c = plane & 511;
    float* sp = s + w * HWSZ;

    const float4* in4 = (const float4*)(xin + (size_t)plane * HWSZ);
    float4* sp4 = (float4*)sp;
    #pragma unroll
    for (int q = lane; q < QPP; q += 32) sp4[q] = in4[q];

    float wq[9];
    const float* wp = dw + c * 9;
    #pragma unroll
    for (int q = 0; q < 9; q++) wq[q] = wp[q];
    __syncwarp();

    cudaGridDependencySynchronize();
    cudaTriggerProgrammaticLaunchCompletion();

    // second-cell scale, lane-parallel gate loads (fresh from k_cell)
    float tg = 0.f;
    if (lane < 3) tg = g_GI[rs][(b * 3 + lane) * CC + c] + g_GH2[rs][lane * CC + c];
    else if (lane == 3) tg = g_C[rs][c];
    float i2  = __shfl_sync(0xffffffffu, tg, 0);
    float f2  = __shfl_sync(0xffffffffu, tg, 1);
    float c2  = __shfl_sync(0xffffffffu, tg, 2);
    float ct0 = __shfl_sync(0xffffffffu, tg, 3);
    float scale = 1.0f + sigmf(sigmf(f2) * ct0 + sigmf(i2) * tanhfast(c2));

    int x = lane;
    bool active = x < WW;
    int xi = active ? x : 0;
    bool notL = (x > 0), notR = (x < WW - 1);

    float aL = 0, aC = 0, aR = 0, bL, bC, bR, cL, cC, cR;
    bC = sp[xi];
    bL = __shfl_up_sync(0xffffffffu, bC, 1);   if (!notL) bL = 0;
    bR = __shfl_down_sync(0xffffffffu, bC, 1); if (!notR) bR = 0;
    cC = sp[WW + xi];
    cL = __shfl_up_sync(0xffffffffu, cC, 1);   if (!notL) cL = 0;
    cR = __shfl_down_sync(0xffffffffu, cC, 1); if (!notR) cR = 0;

    float* outp = xout + (size_t)plane * HWSZ;
    float sum = 0.f;
    #pragma unroll
    for (int y = 0; y < HH; y++) {
        float conv = wq[0] * aL + wq[1] * aC + wq[2] * aR
                   + wq[3] * bL + wq[4] * bC + wq[5] * bR
                   + wq[6] * cL + wq[7] * cC + wq[8] * cR;
        float o = fmaf(bC, scale, conv);
        if (active) { outp[y * WW + x] = o; sum += o; }
        aL = bL; aC = bC; aR = bR;
        bL = cL; bC = cC; bR = cR;
        if (y + 2 < HH) {
            cC = sp[(y + 2) * WW + xi];
            cL = __shfl_up_sync(0xffffffffu, cC, 1);   if (!notL) cL = 0;
            cR = __shfl_down_sync(0xffffffffu, cC, 1); if (!notR) cR = 0;
        } else { cC = cL = cR = 0.f; }
    }
    if (writeSeq) {
        #pragma unroll
        for (int o2 = 16; o2; o2 >>= 1) sum += __shfl_down_sync(0xffffffffu, sum, o2);
        if (lane == 0) g_seq[plane] = sum * (1.0f / HWSZ);
    }
}

extern "C" void kernel_launch(void* const* d_in, const int* in_sizes, int n_in,
                              void* d_out, int out_size) {
    const float* x        = (const float*)d_in[0];
    const float* w_ih_l1  = (const float*)d_in[1];
    const float* b_ih_l1  = (const float*)d_in[2];
    const float* w_ih_l2  = (const float*)d_in[3];
    const float* b_ih_l2  = (const float*)d_in[4];
    const float* w_hh_l1  = (const float*)d_in[5];
    const float* b_hh_l1  = (const float*)d_in[6];
    const float* w_hh_l2  = (const float*)d_in[7];
    const float* b_hh_l2  = (const float*)d_in[8];
    const float* dw       = (const float*)d_in[9];
    float* out = (float*)d_out;

    float* buf = nullptr;
    cudaGetSymbolAddress((void**)&buf, g_buf);

    cudaLaunchAttribute pa;
    pa.id = cudaLaunchAttributeProgrammaticStreamSerialization;
    pa.val.programmaticStreamSerializationAllowed = 1;

    {   // pool (PDL, no internal grid sync -- fully overlapping)
        cudaLaunchConfig_t cfg = {};
        cfg.gridDim = dim3(NUP, 1, 1); cfg.blockDim = dim3(256, 1, 1);
        cfg.attrs = &pa; cfg.numAttrs = 1;
        cudaLaunchKernelEx(&cfg, k_pool, x);
    }

    const float* cur = x;
    for (int l = 0; l < NLAYERS; l++) {
        int ws = l & 1;
        int zero = (l == 0) ? 1 : 0;
        {
            cudaLaunchConfig_t cfg = {};
            cfg.gridDim = dim3(BB, 1, 1); cfg.blockDim = dim3(512, 1, 1);
            cfg.attrs = &pa; cfg.numAttrs = 1;
            cudaLaunchKernelEx(&cfg, k_cell, ws, zero,
                               w_ih_l1, b_ih_l1, w_ih_l2, b_ih_l2,
                               w_hh_l1, b_hh_l1, w_hh_l2, b_hh_l2);
        }
        float* nxt = ((l & 1) == 0) ? buf : out;   // l0->buf, l1->out, l2->buf, l3->out
        int writeSeq = (l < NLAYERS - 1) ? 1 : 0;
        {
            cudaLaunchConfig_t cfg = {};
            cfg.gridDim = dim3(NUP, 1, 1); cfg.blockDim = dim3(256, 1, 1);
            cfg.attrs = &pa; cfg.numAttrs = 1;
            cudaLaunchKernelEx(&cfg, k_update, cur, nxt, dw, ws, writeSeq);
        }
        cur = nxt;
    }
}

// round 10
// speedup vs baseline: 1.8639x; 1.1504x over previous
#include <cuda_runtime.h>

#define BB 64
#define CC 512
#define HH 28
#define WW 28
#define HWSZ (HH*WW)
#define HID 32
#define NPLANE (BB*CC)
#define NLAYERS 4
#define QPP 196            // float4 quads per plane
#define PPB 8              // planes per block (1 warp each)
#define NUP (NPLANE/PPB)   // 4096 update blocks
#define CSUB 4             // cell blocks per batch
#define CCH (CC/CSUB)      // channels per cell block (128)

// Scratch (static device memory -- allocation-free)
__device__ float g_buf[(size_t)NPLANE * HWSZ];   // ping-pong x buffer (~103MB)
__device__ float g_seq[NPLANE];                  // pooled means [B,C]
__device__ float g_H[2][NPLANE];                 // LSTM hidden (double-buffered)
__device__ float g_C[2][NPLANE];                 // LSTM cell
__device__ float g_GI[2][BB * 3 * CC];           // input-path gates
__device__ float g_GH2[2][3 * CC];               // 2nd-cell hidden gates (row 0)
__device__ int   g_cnt = 0;                      // batch-0 arrival counter (self-resetting)

__device__ __forceinline__ float sigmf(float x) { return 1.0f / (1.0f + __expf(-x)); }
__device__ __forceinline__ float tanhfast(float x) {
    float e = __expf(2.0f * x);
    return __fdividef(e - 1.0f, e + 1.0f);
}

// ---------------- pool: warp-per-plane mean of x ----------------
__global__ void __launch_bounds__(256) k_pool(const float* __restrict__ x) {
    int lane = threadIdx.x & 31, w = threadIdx.x >> 5;
    int plane = blockIdx.x * PPB + w;
    const float4* in4 = (const float4*)(x + (size_t)plane * HWSZ);
    float s = 0.f;
    #pragma unroll
    for (int q = lane; q < QPP; q += 32) {
        float4 v = in4[q];
        s += v.x + v.y + v.z + v.w;
    }
    #pragma unroll
    for (int o = 16; o; o >>= 1) s += __shfl_down_sync(0xffffffffu, s, o);
    if (lane == 0) g_seq[plane] = s * (1.0f / HWSZ);
}

// ---------------- cell: 4 blocks per batch, 256 threads each ----------------
// Each block redundantly computes BOTH bottleneck GEMVs for its batch (weights
// are L2-hot), then phase-2 gates for its own 128 channels (2 threads/channel).
// The last-arriving batch-0 block computes the second cell's hidden path.
__global__ void __launch_bounds__(256) k_cell(int ws, int zeroState,
        const float* __restrict__ w_ih_l1, const float* __restrict__ b_ih_l1,
        const float* __restrict__ w_ih_l2, const float* __restrict__ b_ih_l2,
        const float* __restrict__ w_hh_l1, const float* __restrict__ b_hh_l1,
        const float* __restrict__ w_hh_l2, const float* __restrict__ b_hh_l2) {
    __shared__ __align__(16) float sin0[CC], sin1[CC];
    __shared__ __align__(16) float hi[HID], hh[HID];
    __shared__ int sLast;
    int blk = blockIdx.x;
    int b = blk >> 2, sub = blk & 3;
    int tid = threadIdx.x, lane = tid & 31, w = tid >> 5;   // 8 warps
    int rs = 1 - ws;

    // stage ht (prev layer) and seq (just-written by previous kernel)
    if (tid < 128) {
        float4 hv = zeroState ? make_float4(0.f, 0.f, 0.f, 0.f)
                              : ((const float4*)(g_H[rs] + b * CC))[tid];
        ((float4*)sin1)[tid] = hv;
    } else {
        ((float4*)sin0)[tid - 128] = ((const float4*)(g_seq + b * CC))[tid - 128];
    }
    __syncthreads();

    // both GEMVs: 64 dots of length 512, 8 warps x 8 dots
    #pragma unroll
    for (int t = 0; t < 4; t++) {
        int k = t * 8 + w;
        const float4* wr4 = (const float4*)(w_hh_l1 + k * CC);
        float s = 0.f;
        #pragma unroll
        for (int j = lane; j < 128; j += 32) {
            float4 wv = wr4[j], iv = ((const float4*)sin1)[j];
            s += iv.x * wv.x + iv.y * wv.y + iv.z * wv.z + iv.w * wv.w;
        }
        #pragma unroll
        for (int o = 16; o; o >>= 1) s += __shfl_down_sync(0xffffffffu, s, o);
        if (lane == 0) hh[k] = fmaxf(s + b_hh_l1[k], 0.f);
    }
    #pragma unroll
    for (int t = 0; t < 4; t++) {
        int k = t * 8 + w;
        const float4* wr4 = (const float4*)(w_ih_l1 + k * CC);
        float s = 0.f;
        #pragma unroll
        for (int j = lane; j < 128; j += 32) {
            float4 wv = wr4[j], iv = ((const float4*)sin0)[j];
            s += iv.x * wv.x + iv.y * wv.y + iv.z * wv.z + iv.w * wv.w;
        }
        #pragma unroll
        for (int o = 16; o; o >>= 1) s += __shfl_down_sync(0xffffffffu, s, o);
        if (lane == 0) hi[k] = fmaxf(s + b_ih_l1[k], 0.f);
    }
    __syncthreads();

    // phase 2: 128 channels, 2 threads per channel (k split 2x16), shfl combine
    int c = sub * CCH + (tid >> 1);
    int kb = (tid & 1) * 16;                       // 16-wide k slice
    float hir[4][4], hhr[4][4];
    {
        const float4* hi4 = (const float4*)(hi + kb);
        const float4* hh4 = (const float4*)(hh + kb);
        #pragma unroll
        for (int q = 0; q < 4; q++) {
            float4 a = hi4[q]; hir[q][0]=a.x; hir[q][1]=a.y; hir[q][2]=a.z; hir[q][3]=a.w;
            float4 h = hh4[q]; hhr[q][0]=h.x; hhr[q][1]=h.y; hhr[q][2]=h.z; hhr[q][3]=h.w;
        }
    }
    float gi[3], gh[3];
    #pragma unroll
    for (int g = 0; g < 3; g++) {
        const float4* wi4 = (const float4*)&w_ih_l2[(g * CC + c) * HID + kb];
        const float4* wh4 = (const float4*)&w_hh_l2[(g * CC + c) * HID + kb];
        float si = 0.f, sh = 0.f;
        #pragma unroll
        for (int q = 0; q < 4; q++) {
            float4 wi = wi4[q], wh = wh4[q];
            si += hir[q][0]*wi.x + hir[q][1]*wi.y + hir[q][2]*wi.z + hir[q][3]*wi.w;
            sh += hhr[q][0]*wh.x + hhr[q][1]*wh.y + hhr[q][2]*wh.z + hhr[q][3]*wh.w;
        }
        gi[g] = si; gh[g] = sh;
    }
    #pragma unroll
    for (int g = 0; g < 3; g++) {
        gi[g] += __shfl_xor_sync(0xffffffffu, gi[g], 1);
        gh[g] += __shfl_xor_sync(0xffffffffu, gh[g], 1);
    }
    if ((tid & 1) == 0) {
        #pragma unroll
        for (int g = 0; g < 3; g++) {
            gi[g] += b_ih_l2[g * CC + c];
            gh[g] += b_hh_l2[g * CC + c];
            g_GI[ws][(b * 3 + g) * CC + c] = gi[g];
        }
        float ig = sigmf(gi[0] + gh[0]);
        float fg = sigmf(gi[1] + gh[1]);
        float cg = tanhfast(gi[2] + gh[2]);
        float cx = zeroState ? 0.f : g_C[rs][b * CC + c];
        float nc = fg * cx + ig * cg;
        g_C[ws][b * CC + c] = nc;
        g_H[ws][b * CC + c] = sigmf(nc);
    }

    // batch-0 tail: last-arriving batch-0 block computes gh2 from ht[0]
    if (b == 0) {
        __threadfence();
        __syncthreads();
        if (tid == 0) {
            int old = atomicAdd(&g_cnt, 1);
            sLast = (old == CSUB - 1);
            if (sLast) atomicExch(&g_cnt, 0);   // exclusive reset for replay
        }
        __syncthreads();
        if (sLast) {
            if (tid < 128)
                ((float4*)sin1)[tid] = __ldcg(((const float4*)(g_H[ws])) + tid);
            __syncthreads();
            #pragma unroll
            for (int t = 0; t < 4; t++) {
                int k = t * 8 + w;
                const float4* wr4 = (const float4*)(w_hh_l1 + k * CC);
                float s = 0.f;
                #pragma unroll
                for (int j = lane; j < 128; j += 32) {
                    float4 wv = wr4[j], iv = ((const float4*)sin1)[j];
                    s += iv.x * wv.x + iv.y * wv.y + iv.z * wv.z + iv.w * wv.w;
                }
                #pragma unroll
                for (int o = 16; o; o >>= 1) s += __shfl_down_sync(0xffffffffu, s, o);
                if (lane == 0) hh[k] = fmaxf(s + b_hh_l1[k], 0.f);
            }
            __syncthreads();
            #pragma unroll
            for (int j = tid; j < 3 * CC; j += 256) {
                float acc = b_hh_l2[j];
                const float4* wh4 = (const float4*)&w_hh_l2[j * HID];
                #pragma unroll
                for (int q = 0; q < 8; q++) {
                    float4 wh = wh4[q];
                    int k = q * 4;
                    acc += hh[k]*wh.x + hh[k+1]*wh.y + hh[k+2]*wh.z + hh[k+3]*wh.w;
                }
                g_GH2[ws][j] = acc;
            }
        }
    }
}

// ---------------- update: warp-per-plane rolling stencil ----------------
__global__ void __launch_bounds__(256) k_update(
        const float* __restrict__ xin, float* __restrict__ xout,
        const float* __restrict__ dw, int rs, int writeSeq) {
    __shared__ __align__(16) float s[PPB * HWSZ + 4];
    int lane = threadIdx.x & 31, w = threadIdx.x >> 5;
    int plane = blockIdx.x * PPB + w;
    int b = plane >> 9, c = plane & 511;
    float* sp = s + w * HWSZ;

    const float4* in4 = (const float4*)(xin + (size_t)plane * HWSZ);
    float4* sp4 = (float4*)sp;
    #pragma unroll
    for (int q = lane; q < QPP; q += 32) sp4[q] = in4[q];

    // second-cell scale, lane-parallel gate loads
    float tg = 0.f;
    if (lane < 3) tg = g_GI[rs][(b * 3 + lane) * CC + c] + g_GH2[rs][lane * CC + c];
    else if (lane == 3) tg = g_C[rs][c];
    float i2  = __shfl_sync(0xffffffffu, tg, 0);
    float f2  = __shfl_sync(0xffffffffu, tg, 1);
    float c2  = __shfl_sync(0xffffffffu, tg, 2);
    float ct0 = __shfl_sync(0xffffffffu, tg, 3);
    float scale = 1.0f + sigmf(sigmf(f2) * ct0 + sigmf(i2) * tanhfast(c2));

    float wq[9];
    const float* wp = dw + c * 9;
    #pragma unroll
    for (int q = 0; q < 9; q++) wq[q] = wp[q];

    __syncwarp();

    int x = lane;
    bool active = x < WW;
    int xi = active ? x : 0;
    bool notL = (x > 0), notR = (x < WW - 1);

    float aL = 0, aC = 0, aR = 0, bL, bC, bR, cL, cC, cR;
    bC = sp[xi];
    bL = __shfl_up_sync(0xffffffffu, bC, 1);   if (!notL) bL = 0;
    bR = __shfl_down_sync(0xffffffffu, bC, 1); if (!notR) bR = 0;
    cC = sp[WW + xi];
    cL = __shfl_up_sync(0xffffffffu, cC, 1);   if (!notL) cL = 0;
    cR = __shfl_down_sync(0xffffffffu, cC, 1); if (!notR) cR = 0;

    float* outp = xout + (size_t)plane * HWSZ;
    float sum = 0.f;
    #pragma unroll
    for (int y = 0; y < HH; y++) {
        float conv = wq[0] * aL + wq[1] * aC + wq[2] * aR
                   + wq[3] * bL + wq[4] * bC + wq[5] * bR
                   + wq[6] * cL + wq[7] * cC + wq[8] * cR;
        float o = fmaf(bC, scale, conv);
        if (active) { outp[y * WW + x] = o; sum += o; }
        aL = bL; aC = bC; aR = bR;
        bL = cL; bC = cC; bR = cR;
        if (y + 2 < HH) {
            cC = sp[(y + 2) * WW + xi];
            cL = __shfl_up_sync(0xffffffffu, cC, 1);   if (!notL) cL = 0;
            cR = __shfl_down_sync(0xffffffffu, cC, 1); if (!notR) cR = 0;
        } else { cC = cL = cR = 0.f; }
    }
    if (writeSeq) {
        #pragma unroll
        for (int o2 = 16; o2; o2 >>= 1) sum += __shfl_down_sync(0xffffffffu, sum, o2);
        if (lane == 0) g_seq[plane] = sum * (1.0f / HWSZ);
    }
}

extern "C" void kernel_launch(void* const* d_in, const int* in_sizes, int n_in,
                              void* d_out, int out_size) {
    const float* x        = (const float*)d_in[0];
    const float* w_ih_l1  = (const float*)d_in[1];
    const float* b_ih_l1  = (const float*)d_in[2];
    const float* w_ih_l2  = (const float*)d_in[3];
    const float* b_ih_l2  = (const float*)d_in[4];
    const float* w_hh_l1  = (const float*)d_in[5];
    const float* b_hh_l1  = (const float*)d_in[6];
    const float* w_hh_l2  = (const float*)d_in[7];
    const float* b_hh_l2  = (const float*)d_in[8];
    const float* dw       = (const float*)d_in[9];
    float* out = (float*)d_out;

    float* buf = nullptr;
    cudaGetSymbolAddress((void**)&buf, g_buf);

    k_pool<<<NUP, 256>>>(x);

    const float* cur = x;
    for (int l = 0; l < NLAYERS; l++) {
        int ws = l & 1;
        int zero = (l == 0) ? 1 : 0;
        k_cell<<<BB * CSUB, 256>>>(ws, zero,
                                   w_ih_l1, b_ih_l1, w_ih_l2, b_ih_l2,
                                   w_hh_l1, b_hh_l1, w_hh_l2, b_hh_l2);
        float* nxt = ((l & 1) == 0) ? buf : out;   // l0->buf, l1->out, l2->buf, l3->out
        int writeSeq = (l < NLAYERS - 1) ? 1 : 0;
        k_update<<<NUP, 256>>>(cur, nxt, dw, ws, writeSeq);
        cur = nxt;
    }
}